// round 15
// baseline (speedup 1.0000x reference)
#include <cuda_runtime.h>
#include <cuda_bf16.h>
#include <cstdint>

#define HD 128
#define NMAX 100000
#define EMAX 800000
#define SCAN_CHUNK 1024
#define NBLK ((NMAX + SCAN_CHUNK - 1) / SCAN_CHUNK)
#define NSTRIPE 32

// ---------------- scratch ----------------
__device__ __align__(256) float g_L[(size_t)NMAX * HD];
__device__ __align__(256) float g_G[(size_t)NMAX * HD];
__device__ __align__(256) float g_dinv[NMAX];
__device__ __align__(256) float g_selfw[NMAX];
__device__ __align__(256) int   g_cnt[NMAX];
__device__ __align__(256) int   g_rowptr[NMAX + 1];
__device__ __align__(256) int   g_cursor[NMAX];
__device__ __align__(256) int   g_csrc[EMAX];
__device__ __align__(256) float g_cw[EMAX];
__device__ __align__(256) int   g_bsum[NBLK];
__device__ __align__(256) int   g_boff[NBLK];
__device__ __align__(256) float g_sumS[NSTRIPE][HD];
__device__ __align__(256) float g_sqS[NSTRIPE][HD];
__device__ __align__(256) float g_scale[HD];
__device__ __align__(256) float g_shift[HD];
__device__ __align__(256) uint32_t g_WfH[3][8192];
__device__ __align__(256) uint32_t g_WfL[3][8192];

// ---------------- bf16 truncation split ----------------
__device__ __forceinline__ void bf16_split2_trunc(float a, float b, uint32_t& hi, uint32_t& lo) {
    uint32_t au = __float_as_uint(a), bu = __float_as_uint(b);
    hi = __byte_perm(au, bu, 0x7632);
    float ra = a - __uint_as_float(au & 0xFFFF0000u);
    float rb = b - __uint_as_float(bu & 0xFFFF0000u);
    lo = __byte_perm(__float_as_uint(ra), __float_as_uint(rb), 0x7632);
}

// ---------------- CSR build ----------------
__global__ void k_zero_cnt(int N) {
    int i = blockIdx.x * blockDim.x + threadIdx.x;
    if (i < N) g_cnt[i] = 0;
}
__global__ void k_hist(const int* __restrict__ ei, int E) {
    int e = blockIdx.x * blockDim.x + threadIdx.x;
    if (e < E) atomicAdd(&g_cnt[ei[E + e]], 1);
}
__global__ void __launch_bounds__(256) k_blocksum(int N) {
    __shared__ int wsum[8];
    int tid  = threadIdx.x;
    int base = blockIdx.x * SCAN_CHUNK + tid * 4;
    int s = 0;
#pragma unroll
    for (int j = 0; j < 4; j++) {
        int i = base + j;
        if (i < N) {
            int c = g_cnt[i];
            s += c;
            float dv = rsqrtf((float)c + 1.0f);
            g_dinv[i]  = dv;
            g_selfw[i] = dv * dv;
        }
    }
#pragma unroll
    for (int off = 16; off > 0; off >>= 1)
        s += __shfl_down_sync(0xFFFFFFFF, s, off);
    if ((tid & 31) == 0) wsum[tid >> 5] = s;
    __syncthreads();
    if (tid == 0) {
        int t = 0;
#pragma unroll
        for (int w = 0; w < 8; w++) t += wsum[w];
        g_bsum[blockIdx.x] = t;
    }
}
__global__ void __launch_bounds__(128) k_scan_bsum(int E, int N) {
    __shared__ int sv[NBLK];
    int tid = threadIdx.x;
    if (tid < NBLK) sv[tid] = g_bsum[tid];
    // zero striped BN accumulators for layer 0
    for (int s = 0; s < NSTRIPE; s++) {
        g_sumS[s][tid] = 0.f;
        g_sqS[s][tid]  = 0.f;
    }
    __syncthreads();
    if (tid == 0) {
        int run = 0;
        for (int i = 0; i < NBLK; i++) {
            g_boff[i] = run;
            run += sv[i];
        }
        g_rowptr[N] = E;
    }
}
__global__ void __launch_bounds__(256) k_emit(int N) {
    __shared__ int wexc[8];
    int tid  = threadIdx.x;
    int lane = tid & 31;
    int wid  = tid >> 5;
    int base = blockIdx.x * SCAN_CHUNK + tid * 4;
    int c[4];
#pragma unroll
    for (int j = 0; j < 4; j++) {
        int i = base + j;
        c[j] = (i < N) ? g_cnt[i] : 0;
    }
    int tsum = c[0] + c[1] + c[2] + c[3];
    int inc = tsum;
#pragma unroll
    for (int off = 1; off < 32; off <<= 1) {
        int v = __shfl_up_sync(0xFFFFFFFF, inc, off);
        if (lane >= off) inc += v;
    }
    if (lane == 31) wexc[wid] = inc;
    __syncthreads();
    if (tid == 0) {
        int run = 0;
#pragma unroll
        for (int w = 0; w < 8; w++) {
            int t = wexc[w];
            wexc[w] = run;
            run += t;
        }
    }
    __syncthreads();
    int run = g_boff[blockIdx.x] + wexc[wid] + (inc - tsum);
#pragma unroll
    for (int j = 0; j < 4; j++) {
        int i = base + j;
        if (i < N) {
            g_rowptr[i] = run;
            g_cursor[i] = run;
            run += c[j];
        }
    }
}
__global__ void k_fill(const int* __restrict__ ei, int E) {
    int e = blockIdx.x * blockDim.x + threadIdx.x;
    if (e < E) {
        int s = ei[e], d = ei[E + e];
        int pos = atomicAdd(&g_cursor[d], 1);
        g_csrc[pos] = s;
        g_cw[pos]   = g_dinv[s] * g_dinv[d];
    }
}

// ---------------- W fragment prep ----------------
__global__ void k_prep_w(const float* __restrict__ W, uint32_t* __restrict__ WfH,
                         uint32_t* __restrict__ WfL) {
    int i = blockIdx.x * blockDim.x + threadIdx.x;
    if (i >= 8192) return;
    int n = i & 127, kp = i >> 7;
    int k0 = kp * 2;
    float w0 = W[k0 * HD + n];
    float w1 = W[(k0 + 1) * HD + n];
    uint32_t h, l;
    bf16_split2_trunc(w0, w1, h, l);
    int ngroup = n >> 4, ntg = (n >> 3) & 1, grp = n & 7;
    int ck0 = k0 & 15;
    int q = (ck0 & 7) >> 1;
    int reg = ntg * 2 + ((ck0 >= 8) ? 1 : 0);
    int kchunk = k0 >> 4;
    int base = ((ngroup * 8 + kchunk) * 32 + grp * 4 + q) * 4 + reg;
    WfH[base] = h;
    WfL[base] = l;
}

// ---------------- MMA ----------------
__device__ __forceinline__ void mma_bf16(float* c, uint4 a, uint32_t b0, uint32_t b1) {
    asm volatile(
        "mma.sync.aligned.m16n8k16.row.col.f32.bf16.bf16.f32 "
        "{%0,%1,%2,%3}, {%4,%5,%6,%7}, {%8,%9}, {%0,%1,%2,%3};"
        : "+f"(c[0]), "+f"(c[1]), "+f"(c[2]), "+f"(c[3])
        : "r"(a.x), "r"(a.y), "r"(a.z), "r"(a.w), "r"(b0), "r"(b1));
}

// ---------------- GEMM: L = act(A) @ W  (R14-exact) ----------------
#define GEMM_SMEM (2 * 8192 * 4)
#define GEMM_T 512

__global__ void __launch_bounds__(GEMM_T, 2) k_gemm(const float* __restrict__ A,
                                                    const uint32_t* __restrict__ WfH,
                                                    const uint32_t* __restrict__ WfL,
                                                    float* __restrict__ L, int N, int bn) {
    extern __shared__ uint32_t smu[];
    uint32_t* Ah = smu;
    uint32_t* Al = smu + 8192;

    int tid   = threadIdx.x;
    int lane  = tid & 31;
    int wid   = tid >> 5;
    int rbase = blockIdx.x * 128;

    for (int i = tid; i < 4096; i += GEMM_T) {
        int row = i >> 5, q4 = i & 31;
        int gr = rbase + row;
        float4 v = make_float4(0.f, 0.f, 0.f, 0.f);
        if (gr < N) v = ((const float4*)(A + (size_t)gr * HD))[q4];
        if (bn) {
            float4 sc = ((const float4*)g_scale)[q4];
            float4 sh = ((const float4*)g_shift)[q4];
            v.x = fmaxf(v.x * sc.x + sh.x, 0.f);
            v.y = fmaxf(v.y * sc.y + sh.y, 0.f);
            v.z = fmaxf(v.z * sc.z + sh.z, 0.f);
            v.w = fmaxf(v.w * sc.w + sh.w, 0.f);
        }
        int c0     = q4 * 4;
        int mtile  = row >> 4, m = row & 15;
        int kchunk = c0 >> 4,  ck0 = c0 & 15;
        int reg = ((m >= 8) ? 1 : 0) + ((ck0 >= 8) ? 2 : 0);
        int grp = m & 7, qq = (ck0 & 7) >> 1;
        int base = ((mtile * 8 + kchunk) * 32 + grp * 4 + qq) * 4 + reg;
        uint32_t h0, l0, h1, l1;
        bf16_split2_trunc(v.x, v.y, h0, l0);
        bf16_split2_trunc(v.z, v.w, h1, l1);
        Ah[base] = h0;  Al[base] = l0;
        Ah[base + 4] = h1;  Al[base + 4] = l1;
    }
    __syncthreads();

    int mtile = wid >> 1;
    int nhalf = wid & 1;

    float acc[8][4];
#pragma unroll
    for (int j = 0; j < 8; j++)
#pragma unroll
        for (int t = 0; t < 4; t++) acc[j][t] = 0.f;

    const uint4* Ah4 = (const uint4*)Ah;
    const uint4* Al4 = (const uint4*)Al;
    const uint4* BH4 = (const uint4*)WfH;
    const uint4* BL4 = (const uint4*)WfL;

#pragma unroll
    for (int kc = 0; kc < 8; kc++) {
        uint4 ah = Ah4[(mtile * 8 + kc) * 32 + lane];
        uint4 al = Al4[(mtile * 8 + kc) * 32 + lane];
#pragma unroll
        for (int ng = 0; ng < 4; ng++) {
            int ngg = nhalf * 4 + ng;
            uint4 bh = __ldg(&BH4[(ngg * 8 + kc) * 32 + lane]);
            uint4 bl = __ldg(&BL4[(ngg * 8 + kc) * 32 + lane]);
            int j = ng * 2;
            mma_bf16(acc[j],     ah, bh.x, bh.y);
            mma_bf16(acc[j],     al, bh.x, bh.y);
            mma_bf16(acc[j],     ah, bl.x, bl.y);
            mma_bf16(acc[j + 1], ah, bh.z, bh.w);
            mma_bf16(acc[j + 1], al, bh.z, bh.w);
            mma_bf16(acc[j + 1], ah, bl.z, bl.w);
        }
    }

    int grp = lane >> 2, q = lane & 3;
    int r0 = rbase + mtile * 16 + grp;
#pragma unroll
    for (int ng = 0; ng < 4; ng++) {
#pragma unroll
        for (int t = 0; t < 2; t++) {
            int j = ng * 2 + t;
            int col = ((nhalf * 4 + ng) * 2 + t) * 8 + q * 2;
            if (r0 < N)
                *(float2*)&L[(size_t)r0 * HD + col] = make_float2(acc[j][0], acc[j][1]);
            if (r0 + 8 < N)
                *(float2*)&L[(size_t)(r0 + 8) * HD + col] = make_float2(acc[j][2], acc[j][3]);
        }
    }
}

// ---------------- aggregate + striped BN stats (no block sync) ----------------
// one warp per row; after writing its row, the warp fires 2 red.v4 into one of
// 32 striped accumulator copies (stripe = blockIdx & 31).
__global__ void __launch_bounds__(256) k_aggregate(const float* __restrict__ L,
                                                   const float* __restrict__ bias,
                                                   float* __restrict__ G, int N) {
    int wid  = threadIdx.x >> 5;
    int lane = threadIdx.x & 31;
    int row  = blockIdx.x * 8 + wid;
    if (row >= N) return;

    float4 b  = ((const float4*)bias)[lane];
    float  sw = g_selfw[row];
    float4 sv = ((const float4*)(L + (size_t)row * HD))[lane];
    float4 acc;
    acc.x = sv.x * sw + b.x;
    acc.y = sv.y * sw + b.y;
    acc.z = sv.z * sw + b.z;
    acc.w = sv.w * sw + b.w;

    int p0 = g_rowptr[row], p1 = g_rowptr[row + 1];
    for (int p = p0; p < p1; p++) {
        int   s = g_csrc[p];
        float w = g_cw[p];
        float4 v = ((const float4*)(L + (size_t)s * HD))[lane];
        acc.x += v.x * w;
        acc.y += v.y * w;
        acc.z += v.z * w;
        acc.w += v.w * w;
    }
    ((float4*)(G + (size_t)row * HD))[lane] = acc;

    int stripe = blockIdx.x & (NSTRIPE - 1);
    float* sp = &g_sumS[stripe][lane * 4];
    float* qp = &g_sqS[stripe][lane * 4];
    asm volatile("red.global.add.v4.f32 [%0], {%1, %2, %3, %4};" ::
                 "l"(sp), "f"(acc.x), "f"(acc.y), "f"(acc.z), "f"(acc.w) : "memory");
    asm volatile("red.global.add.v4.f32 [%0], {%1, %2, %3, %4};" ::
                 "l"(qp), "f"(acc.x * acc.x), "f"(acc.y * acc.y),
                 "f"(acc.z * acc.z), "f"(acc.w * acc.w) : "memory");
}

// ---------------- BN finalize: reduce 32 stripes, re-zero for next layer ----------------
__global__ void k_bn_final(const float* __restrict__ gamma, const float* __restrict__ beta, int N) {
    int c = threadIdx.x;
    float s = 0.f, q = 0.f;
#pragma unroll
    for (int st = 0; st < NSTRIPE; st++) {
        s += g_sumS[st][c];
        q += g_sqS[st][c];
        g_sumS[st][c] = 0.f;
        g_sqS[st][c]  = 0.f;
    }
    float invn = 1.0f / (float)N;
    float mu   = s * invn;
    float var  = q * invn - mu * mu;
    float sc   = gamma[c] * rsqrtf(var + 1e-5f);
    g_scale[c] = sc;
    g_shift[c] = beta[c] - mu * sc;
}

// ---------------- query ----------------
__global__ void k_query(const float* __restrict__ G, const int* __restrict__ eli,
                        float* __restrict__ out, int Q) {
    int gtid = blockIdx.x * blockDim.x + threadIdx.x;
    int q    = gtid >> 5;
    int lane = gtid & 31;
    if (q >= Q) return;
    int u = eli[q];
    int v = eli[Q + q];
    float4 sc = ((const float4*)g_scale)[lane];
    float4 sh = ((const float4*)g_shift)[lane];
    float4 a = ((const float4*)(G + (size_t)u * HD))[lane];
    float4 b = ((const float4*)(G + (size_t)v * HD))[lane];
    a.x = a.x * sc.x + sh.x; a.y = a.y * sc.y + sh.y;
    a.z = a.z * sc.z + sh.z; a.w = a.w * sc.w + sh.w;
    b.x = b.x * sc.x + sh.x; b.y = b.y * sc.y + sh.y;
    b.z = b.z * sc.z + sh.z; b.w = b.w * sc.w + sh.w;
    float dot = a.x * b.x + a.y * b.y + a.z * b.z + a.w * b.w;
#pragma unroll
    for (int off = 16; off > 0; off >>= 1)
        dot += __shfl_xor_sync(0xFFFFFFFF, dot, off);
    if (lane == 0) out[q] = dot;
}

// ---------------- host ----------------
extern "C" void kernel_launch(void* const* d_in, const int* in_sizes, int n_in,
                              void* d_out, int out_size) {
    const float* x  = (const float*)d_in[0];
    const float* Wl[3] = {(const float*)d_in[1], (const float*)d_in[5], (const float*)d_in[9]};
    const float* bl[3] = {(const float*)d_in[2], (const float*)d_in[6], (const float*)d_in[10]};
    const float* gl[3] = {(const float*)d_in[3], (const float*)d_in[7], (const float*)d_in[11]};
    const float* bel[3]= {(const float*)d_in[4], (const float*)d_in[8], (const float*)d_in[12]};
    const int* ei  = (const int*)d_in[13];
    const int* eli = (const int*)d_in[14];
    float* out = (float*)d_out;

    int N = in_sizes[0] / HD;
    int E = in_sizes[13] / 2;
    int Q = in_sizes[14] / 2;

    float *pL, *pG;
    uint32_t *pWfH, *pWfL;
    cudaGetSymbolAddress((void**)&pL, g_L);
    cudaGetSymbolAddress((void**)&pG, g_G);
    cudaGetSymbolAddress((void**)&pWfH, g_WfH);
    cudaGetSymbolAddress((void**)&pWfL, g_WfL);

    cudaFuncSetAttribute(k_gemm, cudaFuncAttributeMaxDynamicSharedMemorySize, GEMM_SMEM);

    int nblk = (N + SCAN_CHUNK - 1) / SCAN_CHUNK;
    k_zero_cnt<<<(N + 255) / 256, 256>>>(N);
    k_hist<<<(E + 255) / 256, 256>>>(ei, E);
    k_blocksum<<<nblk, 256>>>(N);
    k_scan_bsum<<<1, 128>>>(E, N);
    k_emit<<<nblk, 256>>>(N);
    k_fill<<<(E + 255) / 256, 256>>>(ei, E);
    for (int l = 0; l < 3; l++)
        k_prep_w<<<32, 256>>>(Wl[l], pWfH + l * 8192, pWfL + l * 8192);

    int gemm_blocks = (N + 127) / 128;
    int agg_blocks  = (N + 7) / 8;

    const float* in = x;
    for (int l = 0; l < 3; l++) {
        k_gemm<<<gemm_blocks, GEMM_T, GEMM_SMEM>>>(in, pWfH + l * 8192, pWfL + l * 8192,
                                                   pL, N, l > 0 ? 1 : 0);
        k_aggregate<<<agg_blocks, 256>>>(pL, bl[l], pG, N);
        k_bn_final<<<1, 128>>>(gl[l], bel[l], N);
        in = pG;
    }

    k_query<<<(Q + 7) / 8, 256>>>(pG, eli, out, Q);
}

// round 17
// speedup vs baseline: 1.1869x; 1.1869x over previous
#include <cuda_runtime.h>
#include <cuda_bf16.h>
#include <cstdint>

#define HD 128
#define NMAX 100000
#define EMAX 800000
#define SCAN_CHUNK 1024
#define NBLK ((NMAX + SCAN_CHUNK - 1) / SCAN_CHUNK)

// ---------------- scratch ----------------
__device__ __align__(256) float g_L[(size_t)NMAX * HD];
__device__ __align__(256) float g_G[(size_t)NMAX * HD];
__device__ __align__(256) float g_dinv[NMAX];
__device__ __align__(256) float g_selfw[NMAX];
__device__ __align__(256) int   g_cnt[NMAX];
__device__ __align__(256) int   g_rowptr[NMAX + 1];
__device__ __align__(256) int   g_cursor[NMAX];
__device__ __align__(256) int2  g_epay[EMAX];      // {src, weight_bits} fused payload
__device__ __align__(256) int   g_bsum[NBLK];
__device__ __align__(256) int   g_boff[NBLK];
__device__ __align__(256) float g_sum[HD];
__device__ __align__(256) float g_sq[HD];
__device__ __align__(256) float g_scale[HD];
__device__ __align__(256) float g_shift[HD];
__device__ __align__(256) uint32_t g_WfH[3][8192];
__device__ __align__(256) uint32_t g_WfL[3][8192];

// ---------------- bf16 truncation split ----------------
__device__ __forceinline__ void bf16_split2_trunc(float a, float b, uint32_t& hi, uint32_t& lo) {
    uint32_t au = __float_as_uint(a), bu = __float_as_uint(b);
    hi = __byte_perm(au, bu, 0x7632);
    float ra = a - __uint_as_float(au & 0xFFFF0000u);
    float rb = b - __uint_as_float(bu & 0xFFFF0000u);
    lo = __byte_perm(__float_as_uint(ra), __float_as_uint(rb), 0x7632);
}

// ---------------- CSR build ----------------
__global__ void k_zero_cnt(int N) {
    int i = blockIdx.x * blockDim.x + threadIdx.x;
    if (i < N) g_cnt[i] = 0;
}
__global__ void k_hist(const int* __restrict__ ei, int E) {
    int e = blockIdx.x * blockDim.x + threadIdx.x;
    if (e < E) atomicAdd(&g_cnt[ei[E + e]], 1);
}
__global__ void __launch_bounds__(256) k_blocksum(int N) {
    __shared__ int wsum[8];
    int tid  = threadIdx.x;
    int base = blockIdx.x * SCAN_CHUNK + tid * 4;
    int s = 0;
#pragma unroll
    for (int j = 0; j < 4; j++) {
        int i = base + j;
        if (i < N) {
            int c = g_cnt[i];
            s += c;
            float dv = rsqrtf((float)c + 1.0f);
            g_dinv[i]  = dv;
            g_selfw[i] = dv * dv;
        }
    }
#pragma unroll
    for (int off = 16; off > 0; off >>= 1)
        s += __shfl_down_sync(0xFFFFFFFF, s, off);
    if ((tid & 31) == 0) wsum[tid >> 5] = s;
    __syncthreads();
    if (tid == 0) {
        int t = 0;
#pragma unroll
        for (int w = 0; w < 8; w++) t += wsum[w];
        g_bsum[blockIdx.x] = t;
    }
}
__global__ void __launch_bounds__(128) k_scan_bsum(int E, int N) {
    __shared__ int sv[NBLK];
    int tid = threadIdx.x;
    if (tid < NBLK) sv[tid] = g_bsum[tid];
    g_sum[tid] = 0.f;
    g_sq[tid]  = 0.f;
    __syncthreads();
    if (tid == 0) {
        int run = 0;
        for (int i = 0; i < NBLK; i++) {
            g_boff[i] = run;
            run += sv[i];
        }
        g_rowptr[N] = E;
    }
}
__global__ void __launch_bounds__(256) k_emit(int N) {
    __shared__ int wexc[8];
    int tid  = threadIdx.x;
    int lane = tid & 31;
    int wid  = tid >> 5;
    int base = blockIdx.x * SCAN_CHUNK + tid * 4;
    int c[4];
#pragma unroll
    for (int j = 0; j < 4; j++) {
        int i = base + j;
        c[j] = (i < N) ? g_cnt[i] : 0;
    }
    int tsum = c[0] + c[1] + c[2] + c[3];
    int inc = tsum;
#pragma unroll
    for (int off = 1; off < 32; off <<= 1) {
        int v = __shfl_up_sync(0xFFFFFFFF, inc, off);
        if (lane >= off) inc += v;
    }
    if (lane == 31) wexc[wid] = inc;
    __syncthreads();
    if (tid == 0) {
        int run = 0;
#pragma unroll
        for (int w = 0; w < 8; w++) {
            int t = wexc[w];
            wexc[w] = run;
            run += t;
        }
    }
    __syncthreads();
    int run = g_boff[blockIdx.x] + wexc[wid] + (inc - tsum);
#pragma unroll
    for (int j = 0; j < 4; j++) {
        int i = base + j;
        if (i < N) {
            g_rowptr[i] = run;
            g_cursor[i] = run;
            run += c[j];
        }
    }
}
__global__ void k_fill(const int* __restrict__ ei, int E) {
    int e = blockIdx.x * blockDim.x + threadIdx.x;
    if (e < E) {
        int s = ei[e], d = ei[E + e];
        int pos = atomicAdd(&g_cursor[d], 1);
        float w = g_dinv[s] * g_dinv[d];
        g_epay[pos] = make_int2(s, __float_as_int(w));
    }
}

// ---------------- W fragment prep ----------------
__global__ void k_prep_w(const float* __restrict__ W, uint32_t* __restrict__ WfH,
                         uint32_t* __restrict__ WfL) {
    int i = blockIdx.x * blockDim.x + threadIdx.x;
    if (i >= 8192) return;
    int n = i & 127, kp = i >> 7;
    int k0 = kp * 2;
    float w0 = W[k0 * HD + n];
    float w1 = W[(k0 + 1) * HD + n];
    uint32_t h, l;
    bf16_split2_trunc(w0, w1, h, l);
    int ngroup = n >> 4, ntg = (n >> 3) & 1, grp = n & 7;
    int ck0 = k0 & 15;
    int q = (ck0 & 7) >> 1;
    int reg = ntg * 2 + ((ck0 >= 8) ? 1 : 0);
    int kchunk = k0 >> 4;
    int base = ((ngroup * 8 + kchunk) * 32 + grp * 4 + q) * 4 + reg;
    WfH[base] = h;
    WfL[base] = l;
}

// ---------------- MMA ----------------
__device__ __forceinline__ void mma_bf16(float* c, uint4 a, uint32_t b0, uint32_t b1) {
    asm volatile(
        "mma.sync.aligned.m16n8k16.row.col.f32.bf16.bf16.f32 "
        "{%0,%1,%2,%3}, {%4,%5,%6,%7}, {%8,%9}, {%0,%1,%2,%3};"
        : "+f"(c[0]), "+f"(c[1]), "+f"(c[2]), "+f"(c[3])
        : "r"(a.x), "r"(a.y), "r"(a.z), "r"(a.w), "r"(b0), "r"(b1));
}

// ---------------- GEMM: L = act(A) @ W  (R14-exact) ----------------
#define GEMM_SMEM (2 * 8192 * 4)
#define GEMM_T 512

__global__ void __launch_bounds__(GEMM_T, 2) k_gemm(const float* __restrict__ A,
                                                    const uint32_t* __restrict__ WfH,
                                                    const uint32_t* __restrict__ WfL,
                                                    float* __restrict__ L, int N, int bn) {
    extern __shared__ uint32_t smu[];
    uint32_t* Ah = smu;
    uint32_t* Al = smu + 8192;

    int tid   = threadIdx.x;
    int lane  = tid & 31;
    int wid   = tid >> 5;
    int rbase = blockIdx.x * 128;

    for (int i = tid; i < 4096; i += GEMM_T) {
        int row = i >> 5, q4 = i & 31;
        int gr = rbase + row;
        float4 v = make_float4(0.f, 0.f, 0.f, 0.f);
        if (gr < N) v = ((const float4*)(A + (size_t)gr * HD))[q4];
        if (bn) {
            float4 sc = ((const float4*)g_scale)[q4];
            float4 sh = ((const float4*)g_shift)[q4];
            v.x = fmaxf(v.x * sc.x + sh.x, 0.f);
            v.y = fmaxf(v.y * sc.y + sh.y, 0.f);
            v.z = fmaxf(v.z * sc.z + sh.z, 0.f);
            v.w = fmaxf(v.w * sc.w + sh.w, 0.f);
        }
        int c0     = q4 * 4;
        int mtile  = row >> 4, m = row & 15;
        int kchunk = c0 >> 4,  ck0 = c0 & 15;
        int reg = ((m >= 8) ? 1 : 0) + ((ck0 >= 8) ? 2 : 0);
        int grp = m & 7, qq = (ck0 & 7) >> 1;
        int base = ((mtile * 8 + kchunk) * 32 + grp * 4 + qq) * 4 + reg;
        uint32_t h0, l0, h1, l1;
        bf16_split2_trunc(v.x, v.y, h0, l0);
        bf16_split2_trunc(v.z, v.w, h1, l1);
        Ah[base] = h0;  Al[base] = l0;
        Ah[base + 4] = h1;  Al[base + 4] = l1;
    }
    __syncthreads();

    int mtile = wid >> 1;
    int nhalf = wid & 1;

    float acc[8][4];
#pragma unroll
    for (int j = 0; j < 8; j++)
#pragma unroll
        for (int t = 0; t < 4; t++) acc[j][t] = 0.f;

    const uint4* Ah4 = (const uint4*)Ah;
    const uint4* Al4 = (const uint4*)Al;
    const uint4* BH4 = (const uint4*)WfH;
    const uint4* BL4 = (const uint4*)WfL;

#pragma unroll
    for (int kc = 0; kc < 8; kc++) {
        uint4 ah = Ah4[(mtile * 8 + kc) * 32 + lane];
        uint4 al = Al4[(mtile * 8 + kc) * 32 + lane];
#pragma unroll
        for (int ng = 0; ng < 4; ng++) {
            int ngg = nhalf * 4 + ng;
            uint4 bh = __ldg(&BH4[(ngg * 8 + kc) * 32 + lane]);
            uint4 bl = __ldg(&BL4[(ngg * 8 + kc) * 32 + lane]);
            int j = ng * 2;
            mma_bf16(acc[j],     ah, bh.x, bh.y);
            mma_bf16(acc[j],     al, bh.x, bh.y);
            mma_bf16(acc[j],     ah, bl.x, bl.y);
            mma_bf16(acc[j + 1], ah, bh.z, bh.w);
            mma_bf16(acc[j + 1], al, bh.z, bh.w);
            mma_bf16(acc[j + 1], ah, bl.z, bl.w);
        }
    }

    int grp = lane >> 2, q = lane & 3;
    int r0 = rbase + mtile * 16 + grp;
#pragma unroll
    for (int ng = 0; ng < 4; ng++) {
#pragma unroll
        for (int t = 0; t < 2; t++) {
            int j = ng * 2 + t;
            int col = ((nhalf * 4 + ng) * 2 + t) * 8 + q * 2;
            if (r0 < N)
                *(float2*)&L[(size_t)r0 * HD + col] = make_float2(acc[j][0], acc[j][1]);
            if (r0 + 8 < N)
                *(float2*)&L[(size_t)(r0 + 8) * HD + col] = make_float2(acc[j][2], acc[j][3]);
        }
    }
}

// ---------------- aggregate (R6-structure, int2 payload): one warp per row ----------------
__global__ void __launch_bounds__(256) k_aggregate(const float* __restrict__ L,
                                                   const float* __restrict__ bias,
                                                   float* __restrict__ G, int N) {
    int wid  = threadIdx.x >> 5;
    int lane = threadIdx.x & 31;
    int row  = blockIdx.x * 8 + wid;
    if (row >= N) return;

    float4 b  = ((const float4*)bias)[lane];
    float  sw = g_selfw[row];
    float4 sv = ((const float4*)(L + (size_t)row * HD))[lane];
    float4 acc;
    acc.x = sv.x * sw + b.x;
    acc.y = sv.y * sw + b.y;
    acc.z = sv.z * sw + b.z;
    acc.w = sv.w * sw + b.w;

    int p0 = g_rowptr[row], p1 = g_rowptr[row + 1];
    for (int p = p0; p < p1; p++) {
        int2  pay = g_epay[p];
        float w   = __int_as_float(pay.y);
        float4 v = ((const float4*)(L + (size_t)pay.x * HD))[lane];
        acc.x += v.x * w;
        acc.y += v.y * w;
        acc.z += v.z * w;
        acc.w += v.w * w;
    }
    ((float4*)(G + (size_t)row * HD))[lane] = acc;
}

// ---------------- BN stats (separate, R14-exact) ----------------
#define STAT_ROWS 128
__global__ void k_stats(const float* __restrict__ G, int N) {
    int c  = threadIdx.x;
    int r0 = blockIdx.x * STAT_ROWS;
    int r1 = min(r0 + STAT_ROWS, N);
    float s = 0.f, q = 0.f;
    for (int r = r0; r < r1; r++) {
        float v = G[(size_t)r * HD + c];
        s += v;
        q += v * v;
    }
    atomicAdd(&g_sum[c], s);
    atomicAdd(&g_sq[c], q);
}
__global__ void k_bn_final(const float* __restrict__ gamma, const float* __restrict__ beta, int N) {
    int c = threadIdx.x;
    float invn = 1.0f / (float)N;
    float mu   = g_sum[c] * invn;
    float var  = g_sq[c] * invn - mu * mu;
    float sc   = gamma[c] * rsqrtf(var + 1e-5f);
    g_scale[c] = sc;
    g_shift[c] = beta[c] - mu * sc;
    g_sum[c] = 0.f;
    g_sq[c]  = 0.f;
}

// ---------------- query ----------------
__global__ void k_query(const float* __restrict__ G, const int* __restrict__ eli,
                        float* __restrict__ out, int Q) {
    int gtid = blockIdx.x * blockDim.x + threadIdx.x;
    int q    = gtid >> 5;
    int lane = gtid & 31;
    if (q >= Q) return;
    int u = eli[q];
    int v = eli[Q + q];
    float4 sc = ((const float4*)g_scale)[lane];
    float4 sh = ((const float4*)g_shift)[lane];
    float4 a = ((const float4*)(G + (size_t)u * HD))[lane];
    float4 b = ((const float4*)(G + (size_t)v * HD))[lane];
    a.x = a.x * sc.x + sh.x; a.y = a.y * sc.y + sh.y;
    a.z = a.z * sc.z + sh.z; a.w = a.w * sc.w + sh.w;
    b.x = b.x * sc.x + sh.x; b.y = b.y * sc.y + sh.y;
    b.z = b.z * sc.z + sh.z; b.w = b.w * sc.w + sh.w;
    float dot = a.x * b.x + a.y * b.y + a.z * b.z + a.w * b.w;
#pragma unroll
    for (int off = 16; off > 0; off >>= 1)
        dot += __shfl_xor_sync(0xFFFFFFFF, dot, off);
    if (lane == 0) out[q] = dot;
}

// ---------------- host ----------------
extern "C" void kernel_launch(void* const* d_in, const int* in_sizes, int n_in,
                              void* d_out, int out_size) {
    const float* x  = (const float*)d_in[0];
    const float* Wl[3] = {(const float*)d_in[1], (const float*)d_in[5], (const float*)d_in[9]};
    const float* bl[3] = {(const float*)d_in[2], (const float*)d_in[6], (const float*)d_in[10]};
    const float* gl[3] = {(const float*)d_in[3], (const float*)d_in[7], (const float*)d_in[11]};
    const float* bel[3]= {(const float*)d_in[4], (const float*)d_in[8], (const float*)d_in[12]};
    const int* ei  = (const int*)d_in[13];
    const int* eli = (const int*)d_in[14];
    float* out = (float*)d_out;

    int N = in_sizes[0] / HD;
    int E = in_sizes[13] / 2;
    int Q = in_sizes[14] / 2;

    float *pL, *pG;
    uint32_t *pWfH, *pWfL;
    cudaGetSymbolAddress((void**)&pL, g_L);
    cudaGetSymbolAddress((void**)&pG, g_G);
    cudaGetSymbolAddress((void**)&pWfH, g_WfH);
    cudaGetSymbolAddress((void**)&pWfL, g_WfL);

    cudaFuncSetAttribute(k_gemm, cudaFuncAttributeMaxDynamicSharedMemorySize, GEMM_SMEM);

    int nblk = (N + SCAN_CHUNK - 1) / SCAN_CHUNK;
    k_zero_cnt<<<(N + 255) / 256, 256>>>(N);
    k_hist<<<(E + 255) / 256, 256>>>(ei, E);
    k_blocksum<<<nblk, 256>>>(N);
    k_scan_bsum<<<1, 128>>>(E, N);
    k_emit<<<nblk, 256>>>(N);
    k_fill<<<(E + 255) / 256, 256>>>(ei, E);
    for (int l = 0; l < 3; l++)
        k_prep_w<<<32, 256>>>(Wl[l], pWfH + l * 8192, pWfL + l * 8192);

    int gemm_blocks = (N + 127) / 128;
    int agg_blocks  = (N + 7) / 8;
    int stat_blocks = (N + STAT_ROWS - 1) / STAT_ROWS;

    const float* in = x;
    for (int l = 0; l < 3; l++) {
        k_gemm<<<gemm_blocks, GEMM_T, GEMM_SMEM>>>(in, pWfH + l * 8192, pWfL + l * 8192,
                                                   pL, N, l > 0 ? 1 : 0);
        k_aggregate<<<agg_blocks, 256>>>(pL, bl[l], pG, N);
        k_stats<<<stat_blocks, 128>>>(pG, N);
        k_bn_final<<<1, 128>>>(gl[l], bel[l], N);
        in = pG;
    }

    k_query<<<(Q + 7) / 8, 256>>>(pG, eli, out, Q);
}